// round 8
// baseline (speedup 1.0000x reference)
#include <cuda_runtime.h>
#include <cuda_pipeline.h>
#include <cstdint>
#include <cstddef>

#define BB 1024
#define TT 1024
#define NN 34
#define BPB 2                      // batches per block (forward)
#define FWD_THREADS (BPB * NN)     // 68 threads
#define FWD_BLOCKS  (BB / BPB)     // 512 CTAs, exact

#define CH 8                       // t-steps per bp-build chunk
#define NCH (TT / CH)              // 128 chunks
#define BPT_THREADS (CH * NN)      // 272 threads

// Score history: row r of batch b = S_{r-1} (row 0 = init). [B][T+1][N]
__device__ float g_S[(size_t)BB * (TT + 1) * NN];
// Backpointers u8 [b][t][j]
__device__ unsigned char g_bp[(size_t)BB * TT * NN];
__device__ int g_idx[BB];

__device__ __forceinline__ unsigned long long addx2(unsigned long long a, unsigned long long b) {
    unsigned long long r;
    asm("add.rn.f32x2 %0, %1, %2;" : "=l"(r) : "l"(a), "l"(b));
    return r;
}
__device__ __forceinline__ unsigned long long packff(float f) {
    unsigned long long r; unsigned u = __float_as_uint(f);
    asm("mov.b64 %0, {%1, %1};" : "=l"(r) : "r"(u));
    return r;
}
__device__ __forceinline__ void unpk(unsigned long long v, float& lo, float& hi) {
    unsigned a, b;
    asm("mov.b64 {%0, %1}, %2;" : "=r"(a), "=r"(b) : "l"(v));
    lo = __uint_as_float(a); hi = __uint_as_float(b);
}

// ---------------- forward: scores only (no argmax work) ----------------
__global__ __launch_bounds__(FWD_THREADS)
void viterbi_fwd(const float* __restrict__ feat,
                 const float* __restrict__ trans,
                 float* __restrict__ out)
{
    const int tid = threadIdx.x;
    const int bl  = tid / NN;
    const int j   = tid % NN;
    const int b   = blockIdx.x * BPB + bl;

    __shared__ __align__(16) float sc[2][BPB][36];
    __shared__ float tend[NN];
    __shared__ float fin[BPB][NN];

    unsigned long long trp[17];
#pragma unroll
    for (int i = 0; i < 17; i++) {
        unsigned lo = __float_as_uint(trans[j * NN + 2 * i]);
        unsigned hi = __float_as_uint(trans[j * NN + 2 * i + 1]);
        asm("mov.b64 %0, {%1, %2};" : "=l"(trp[i]) : "r"(lo), "r"(hi));
    }
    if (tid < NN) tend[tid] = trans[(NN - 1) * NN + tid];

    const float init = (j == NN - 2) ? 0.0f : -6969.0f;
    sc[0][bl][j] = init;
    g_S[((size_t)b * (TT + 1)) * NN + j] = init;
    __syncthreads();

    const size_t fbase = (size_t)b * ((size_t)TT * NN) + j;
    const float* fp = feat + fbase;
    float* sp_out = g_S + ((size_t)b * (TT + 1) + 1) * NN + j;

    float fring[4];
#pragma unroll
    for (int u = 0; u < 4; u++) fring[u] = __ldg(fp + (size_t)u * NN);
    fp += (size_t)4 * NN;

    int cur = 0;
#pragma unroll 1
    for (int tb = 0; tb < TT; tb += 4) {
#pragma unroll
        for (int u = 0; u < 4; u++) {
            const int t = tb + u;
            float f = fring[u];
            float fn = 0.0f;
            if (t + 4 < TT) fn = __ldg(fp);
            fp += NN;
            fring[u] = fn;

            const ulonglong2* sp2 = (const ulonglong2*)&sc[cur][bl][0];
            unsigned long long ff = packff(f);

            float m[NN];
#pragma unroll
            for (int i = 0; i < 8; i++) {
                ulonglong2 q = sp2[i];
                unsigned long long v0 = addx2(addx2(q.x, ff), trp[2 * i]);
                unsigned long long v1 = addx2(addx2(q.y, ff), trp[2 * i + 1]);
                unpk(v0, m[4 * i], m[4 * i + 1]);
                unpk(v1, m[4 * i + 2], m[4 * i + 3]);
            }
            {
                unsigned long long q = *(const unsigned long long*)&sc[cur][bl][32];
                unsigned long long v = addx2(addx2(q, ff), trp[16]);
                unpk(v, m[32], m[33]);
            }
#pragma unroll
            for (int s = 1; s < NN; s <<= 1)
#pragma unroll
                for (int k = 0; k + s < NN; k += (s << 1))
                    m[k] = fmaxf(m[k], m[k + s]);

            sc[cur ^ 1][bl][j] = m[0];
            *sp_out = m[0];
            sp_out += NN;
            cur ^= 1;
            __syncthreads();
        }
    }

    fin[bl][j] = sc[cur][bl][j] + tend[j];
    __syncthreads();
    if (j == 0) {
        float bm = -3.4e38f; int bi = 0;
#pragma unroll
        for (int k = 0; k < NN; k++) {
            float v = fin[bl][k];
            if (v > bm) { bm = v; bi = k; }
        }
        out[b] = bm;
        g_idx[b] = bi;
    }
}

// ------------- bp-build: fully parallel equality matching -------------
// block = batch; 272 threads = 8 t-slots x 34 j. cp.async double-buffered
// staging of contiguous S (9 rows) + feat (8 rows) segments per chunk.
__global__ __launch_bounds__(BPT_THREADS)
void bp_build(const float* __restrict__ feat,
              const float* __restrict__ trans)
{
    const int b   = blockIdx.x;
    const int tid = threadIdx.x;
    const int s   = tid / NN;       // t-slot 0..7
    const int j   = tid % NN;

    __shared__ __align__(16) float SBUF[2][(CH + 1) * NN];  // 306 floats
    __shared__ __align__(16) float FBUF[2][CH * NN];        // 272 floats

    // trans row j packed (reused for all 1024 t)
    unsigned long long trp[17];
#pragma unroll
    for (int i = 0; i < 17; i++) {
        unsigned lo = __float_as_uint(trans[j * NN + 2 * i]);
        unsigned hi = __float_as_uint(trans[j * NN + 2 * i + 1]);
        asm("mov.b64 %0, {%1, %2};" : "=l"(trp[i]) : "r"(lo), "r"(hi));
    }

    const float* Sb = g_S + (size_t)b * (TT + 1) * NN;   // row r = S_{r-1}
    const float* Fb = feat + (size_t)b * TT * NN;
    unsigned char* bpb = g_bp + (size_t)b * TT * NN;

    // stage chunk `c` into buffer pb (8-byte cp.async; both segments 8B-aligned)
    auto stage = [&](int c, int pb) {
        const double* sS = (const double*)(Sb + (size_t)c * CH * NN);  // 9 rows
        double* dS = (double*)SBUF[pb];
        for (int i = tid; i < (CH + 1) * NN / 2; i += BPT_THREADS)
            __pipeline_memcpy_async(dS + i, sS + i, 8);
        const double* sF = (const double*)(Fb + (size_t)c * CH * NN);  // 8 rows
        double* dF = (double*)FBUF[pb];
        for (int i = tid; i < CH * NN / 2; i += BPT_THREADS)
            __pipeline_memcpy_async(dF + i, sF + i, 8);
    };

    stage(0, 0);
    __pipeline_commit();

    int buf = 0;
#pragma unroll 1
    for (int c = 0; c < NCH; c++) {
        if (c + 1 < NCH) { stage(c + 1, buf ^ 1); }
        __pipeline_commit();
        __pipeline_wait_prior(1);          // chunk c resident
        __syncthreads();

        const float f   = FBUF[buf][s * NN + j];
        const float tgt = SBUF[buf][(s + 1) * NN + j];   // S_t[j]
        unsigned long long ff = packff(f);

        const unsigned long long* srow = (const unsigned long long*)&SBUF[buf][s * NN];
        int e[17];
#pragma unroll
        for (int i = 0; i < 17; i++) {
            float c0, c1;
            unsigned long long v = addx2(addx2(srow[i], ff), trp[i]);
            unpk(v, c0, c1);
            int lo = (c0 == tgt) ? (2 * i)     : 63;
            int hi = (c1 == tgt) ? (2 * i + 1) : 63;
            e[i] = lo < hi ? lo : hi;
        }
#pragma unroll
        for (int st = 1; st < 17; st <<= 1)
#pragma unroll
            for (int k = 0; k + st < 17; k += (st << 1))
                e[k] = e[k] < e[k + st] ? e[k] : e[k + st];

        bpb[(size_t)(c * CH + s) * NN + j] = (unsigned char)e[0];

        __syncthreads();                   // protect buf before restage
        buf ^= 1;
    }
}

// ---------------- chase (proven, ~48 us) ----------------
__global__ __launch_bounds__(256)
void viterbi_back(float* __restrict__ out)
{
    __shared__ unsigned char bp[TT * NN];
    const int b = blockIdx.x;

    const uint4* src = (const uint4*)(g_bp + (size_t)b * ((size_t)TT * NN));
    uint4* dst = (uint4*)bp;
    for (int i = threadIdx.x; i < (TT * NN) / 16; i += 256) dst[i] = src[i];
    __syncthreads();

    if (threadIdx.x == 0) {
        int i = g_idx[b];
        float* path = out + BB + (size_t)b * (TT + 1);
        path[TT] = (float)i;
        for (int t = TT - 1; t >= 0; t--) {
            i = bp[t * NN + i];
            path[t] = (float)i;
        }
    }
}

extern "C" void kernel_launch(void* const* d_in, const int* in_sizes, int n_in,
                              void* d_out, int out_size)
{
    const float* feat  = (const float*)d_in[0];
    const float* trans = (const float*)d_in[1];
    if (n_in >= 2 && in_sizes[0] == NN * NN) {
        feat  = (const float*)d_in[1];
        trans = (const float*)d_in[0];
    }
    float* out = (float*)d_out;

    viterbi_fwd<<<FWD_BLOCKS, FWD_THREADS>>>(feat, trans, out);
    bp_build<<<BB, BPT_THREADS>>>(feat, trans);
    viterbi_back<<<BB, 256>>>(out);
}

// round 9
// speedup vs baseline: 1.0183x; 1.0183x over previous
#include <cuda_runtime.h>
#include <cuda_pipeline.h>
#include <cstdint>
#include <cstddef>

#define BB 1024
#define TT 1024
#define NN 34
#define BPB 2                      // batches per block (forward)
#define FWD_THREADS (BPB * NN)     // 68 threads
#define FWD_BLOCKS  592            // 4 CTAs/SM balanced (proven fastest); tail clamps

#define CH 8                       // t-steps per chunk
#define NCH (TT / CH)              // 128 chunks
#define NSLOT 5                    // cp.async ring depth
#define BPT_THREADS (CH * NN)      // 272 threads

// Score history: row r of batch b = S_{r-1} (row 0 = init). [B][T+1][N]
__device__ float g_S[(size_t)BB * (TT + 1) * NN];
__device__ int g_idx[BB];

__device__ __forceinline__ unsigned long long addx2(unsigned long long a, unsigned long long b) {
    unsigned long long r;
    asm("add.rn.f32x2 %0, %1, %2;" : "=l"(r) : "l"(a), "l"(b));
    return r;
}
__device__ __forceinline__ unsigned long long packff(float f) {
    unsigned long long r; unsigned u = __float_as_uint(f);
    asm("mov.b64 %0, {%1, %1};" : "=l"(r) : "r"(u));
    return r;
}
__device__ __forceinline__ void unpk(unsigned long long v, float& lo, float& hi) {
    unsigned a, b;
    asm("mov.b64 {%0, %1}, %2;" : "=r"(a), "=r"(b) : "l"(v));
    lo = __uint_as_float(a); hi = __uint_as_float(b);
}

// ---------------- forward: scores only (round-5 proven config) ----------------
__global__ __launch_bounds__(FWD_THREADS)
void viterbi_fwd(const float* __restrict__ feat,
                 const float* __restrict__ trans,
                 float* __restrict__ out)
{
    const int tid = threadIdx.x;
    const int bl  = tid / NN;
    const int j   = tid % NN;
    int b = blockIdx.x * BPB + bl;
    if (b >= BB) b = BB - 1;       // tail CTAs duplicate batch 1023: identical writes, benign

    __shared__ __align__(16) float sc[2][BPB][36];
    __shared__ float tend[NN];
    __shared__ float fin[BPB][NN];

    unsigned long long trp[17];
#pragma unroll
    for (int i = 0; i < 17; i++) {
        unsigned lo = __float_as_uint(trans[j * NN + 2 * i]);
        unsigned hi = __float_as_uint(trans[j * NN + 2 * i + 1]);
        asm("mov.b64 %0, {%1, %2};" : "=l"(trp[i]) : "r"(lo), "r"(hi));
    }
    if (tid < NN) tend[tid] = trans[(NN - 1) * NN + tid];

    const float init = (j == NN - 2) ? 0.0f : -6969.0f;
    sc[0][bl][j] = init;
    g_S[((size_t)b * (TT + 1)) * NN + j] = init;
    __syncthreads();

    const size_t fbase = (size_t)b * ((size_t)TT * NN) + j;
    const float* fp = feat + fbase;
    float* sp_out = g_S + ((size_t)b * (TT + 1) + 1) * NN + j;

    float fring[4];
#pragma unroll
    for (int u = 0; u < 4; u++) fring[u] = __ldg(fp + (size_t)u * NN);
    fp += (size_t)4 * NN;

    int cur = 0;
#pragma unroll 1
    for (int tb = 0; tb < TT; tb += 4) {
#pragma unroll
        for (int u = 0; u < 4; u++) {
            const int t = tb + u;
            float f = fring[u];
            float fn = 0.0f;
            if (t + 4 < TT) fn = __ldg(fp);
            fp += NN;
            fring[u] = fn;

            const ulonglong2* sp2 = (const ulonglong2*)&sc[cur][bl][0];
            unsigned long long ff = packff(f);

            float m[NN];
#pragma unroll
            for (int i = 0; i < 8; i++) {
                ulonglong2 q = sp2[i];
                unsigned long long v0 = addx2(addx2(q.x, ff), trp[2 * i]);
                unsigned long long v1 = addx2(addx2(q.y, ff), trp[2 * i + 1]);
                unpk(v0, m[4 * i], m[4 * i + 1]);
                unpk(v1, m[4 * i + 2], m[4 * i + 3]);
            }
            {
                unsigned long long q = *(const unsigned long long*)&sc[cur][bl][32];
                unsigned long long v = addx2(addx2(q, ff), trp[16]);
                unpk(v, m[32], m[33]);
            }
#pragma unroll
            for (int s = 1; s < NN; s <<= 1)
#pragma unroll
                for (int k = 0; k + s < NN; k += (s << 1))
                    m[k] = fmaxf(m[k], m[k + s]);

            sc[cur ^ 1][bl][j] = m[0];
            *sp_out = m[0];
            sp_out += NN;
            cur ^= 1;
            __syncthreads();
        }
    }

    fin[bl][j] = sc[cur][bl][j] + tend[j];
    __syncthreads();
    if (j == 0) {
        float bm = -3.4e38f; int bi = 0;
#pragma unroll
        for (int k = 0; k < NN; k++) {
            float v = fin[bl][k];
            if (v > bm) { bm = v; bi = k; }
        }
        out[b] = bm;
        g_idx[b] = bi;
    }
}

// -------- fused bp-build + chase: block per batch, bp stays in smem --------
#define SSEG ((CH + 1) * NN)       // 306 floats: S rows c*8 .. c*8+8
#define FSEG (CH * NN)             // 272 floats: feat rows

__global__ __launch_bounds__(BPT_THREADS)
void bp_chase(const float* __restrict__ feat,
              const float* __restrict__ trans,
              float* __restrict__ out)
{
    const int b   = blockIdx.x;
    const int tid = threadIdx.x;
    const int s   = tid / NN;       // t-slot 0..7
    const int j   = tid % NN;

    __shared__ __align__(16) float SBUF[NSLOT][SSEG];   // 5*1224B
    __shared__ __align__(16) float FBUF[NSLOT][FSEG];   // 5*1088B
    __shared__ unsigned char bp[TT * NN];               // 34816B

    // trans row j packed (fixed per thread)
    unsigned long long trp[17];
#pragma unroll
    for (int i = 0; i < 17; i++) {
        unsigned lo = __float_as_uint(trans[j * NN + 2 * i]);
        unsigned hi = __float_as_uint(trans[j * NN + 2 * i + 1]);
        asm("mov.b64 %0, {%1, %2};" : "=l"(trp[i]) : "r"(lo), "r"(hi));
    }

    const float* Sb = g_S + (size_t)b * (TT + 1) * NN;   // row r = S_{r-1}
    const float* Fb = feat + (size_t)b * TT * NN;

    auto stage = [&](int c) {
        const int sl = c % NSLOT;
        const double* sS = (const double*)(Sb + (size_t)c * CH * NN);
        double* dS = (double*)SBUF[sl];
        for (int i = tid; i < SSEG / 2; i += BPT_THREADS)
            __pipeline_memcpy_async(dS + i, sS + i, 8);
        const double* sF = (const double*)(Fb + (size_t)c * CH * NN);
        double* dF = (double*)FBUF[sl];
        for (int i = tid; i < FSEG / 2; i += BPT_THREADS)
            __pipeline_memcpy_async(dF + i, sF + i, 8);
        __pipeline_commit();
    };

    // prologue: stage chunks 0..3
#pragma unroll
    for (int c = 0; c < 4; c++) stage(c);

#pragma unroll 1
    for (int c = 0; c < NCH; c++) {
        const int sl = c % NSLOT;
        __pipeline_wait_prior(3);          // chunk c resident
        __syncthreads();                   // visible to all; prior slot reuse safe
        if (c + 4 < NCH) stage(c + 4);     // into slot (c+4)%5 = (c-1)%5, now free

        const float f   = FBUF[sl][s * NN + j];
        const float tgt = SBUF[sl][(s + 1) * NN + j];   // S_t[j]
        unsigned long long ff = packff(f);

        const unsigned long long* srow = (const unsigned long long*)&SBUF[sl][s * NN];
        int e[17];
#pragma unroll
        for (int i = 0; i < 17; i++) {
            float c0, c1;
            unsigned long long v = addx2(addx2(srow[i], ff), trp[i]);
            unpk(v, c0, c1);
            int lo = (c0 == tgt) ? (2 * i)     : 63;
            int hi = (c1 == tgt) ? (2 * i + 1) : 63;
            e[i] = lo < hi ? lo : hi;
        }
#pragma unroll
        for (int st = 1; st < 17; st <<= 1)
#pragma unroll
            for (int k = 0; k + st < 17; k += (st << 1))
                e[k] = e[k] < e[k + st] ? e[k] : e[k + st];

        bp[(c * CH + s) * NN + j] = (unsigned char)e[0];
    }

    __syncthreads();

    // serial walk over smem bp (overlapped across the 1024 blocks)
    if (tid == 0) {
        int i = g_idx[b];
        float* path = out + BB + (size_t)b * (TT + 1);
        path[TT] = (float)i;
        for (int t = TT - 1; t >= 0; t--) {
            i = bp[t * NN + i];
            path[t] = (float)i;
        }
    }
}

extern "C" void kernel_launch(void* const* d_in, const int* in_sizes, int n_in,
                              void* d_out, int out_size)
{
    const float* feat  = (const float*)d_in[0];
    const float* trans = (const float*)d_in[1];
    if (n_in >= 2 && in_sizes[0] == NN * NN) {
        feat  = (const float*)d_in[1];
        trans = (const float*)d_in[0];
    }
    float* out = (float*)d_out;

    viterbi_fwd<<<FWD_BLOCKS, FWD_THREADS>>>(feat, trans, out);
    bp_chase<<<BB, BPT_THREADS>>>(feat, trans, out);
}